// round 15
// baseline (speedup 1.0000x reference)
#include <cuda_runtime.h>
#include <cuda_fp16.h>
#include <math.h>
#include <stdint.h>

// Problem constants
#define Bsz 32
#define Ssz 512
#define Dsz 512
#define Hh  8
#define HDim 64
#define Mrows (Bsz*Ssz)          // 16384
#define NEG_SLOPE 0.2f

// ---------------------------------------------------------------------------
// Scratch (static __device__ arrays; allocation is forbidden)
// ---------------------------------------------------------------------------
__device__ __half g_x16 [Mrows*Dsz];         // x in fp16
__device__ __half g_w16 [Dsz*Dsz];           // w_W fp16
__device__ __half g_f1w16[2*Dsz*Dsz];        // ff1_W fp16
__device__ __half g_f2w16[2*Dsz*Dsz];        // ff2_W fp16
__device__ __half g_hT  [Bsz*Hh*HDim*Ssz];   // (bh, d, s) fp16 transposed heads
__device__ float  g_src [Bsz*Hh*Ssz];
__device__ float  g_dst [Bsz*Hh*Ssz];
__device__ int    g_perm[Bsz*Hh*Ssz];        // sorted order (rank -> j)
__device__ int    g_rows[Bsz*Hh*Ssz];        // rows bucketed by cut point
__device__ int    g_kstart[Bsz*Hh*513];      // bucket offsets
__device__ float  g_a1  [Bsz*Hh*Ssz];        // e^{s_i}/Z_i
__device__ float  g_a2  [Bsz*Hh*Ssz];        // e^{0.2 s_i}/Z_i
__device__ float  g_att [Bsz*Hh*Ssz*HDim];   // attention output fp32
__device__ float  g_y   [Mrows*Dsz];         // post-LN1 fp32 (residual for EPI3)
__device__ __half g_y16 [Mrows*Dsz];         // post-LN1 fp16 (mm2 input)
__device__ __half g_ff16[Mrows*2*Dsz];       // GeLU(ff1) fp16 (mm3 input)
__device__ float  g_pre2[Mrows*Dsz];         // ff2 out + residual (pre-LN2)

// ---------------------------------------------------------------------------
// helpers
// ---------------------------------------------------------------------------
__device__ __forceinline__ uint32_t pack2h(float x, float y) {
    __half2 h = __floats2half2_rn(x, y);
    return *reinterpret_cast<uint32_t*>(&h);
}
__device__ __forceinline__ uint32_t sm32(const void* p) {
    return (uint32_t)__cvta_generic_to_shared(p);
}
__device__ __forceinline__ void mma16(float* c, const uint32_t* a, const uint32_t* b) {
    asm volatile(
        "mma.sync.aligned.m16n8k16.row.col.f32.f16.f16.f32 "
        "{%0,%1,%2,%3}, {%4,%5,%6,%7}, {%8,%9}, {%0,%1,%2,%3};"
        : "+f"(c[0]), "+f"(c[1]), "+f"(c[2]), "+f"(c[3])
        : "r"(a[0]), "r"(a[1]), "r"(a[2]), "r"(a[3]), "r"(b[0]), "r"(b[1]));
}
__device__ __forceinline__ void ldm_x4(uint32_t* r, uint32_t saddr) {
    asm volatile(
        "ldmatrix.sync.aligned.m8n8.x4.shared.b16 {%0,%1,%2,%3}, [%4];"
        : "=r"(r[0]), "=r"(r[1]), "=r"(r[2]), "=r"(r[3]) : "r"(saddr));
}
#define CP16(sa, ga) asm volatile("cp.async.cg.shared.global [%0], [%1], 16;" :: "r"(sa), "l"(ga))
#define CPCOMMIT()   asm volatile("cp.async.commit_group;" ::: "memory")
#define CPWAIT1()    asm volatile("cp.async.wait_group 1;" ::: "memory")
#define CPWAIT0()    asm volatile("cp.async.wait_group 0;" ::: "memory")

// ---------------------------------------------------------------------------
// fused fp32 -> fp16 conversion of 4 arrays (all sizes % 1024 == 0)
// ---------------------------------------------------------------------------
__global__ __launch_bounds__(256) void f2h4_kernel(
    const float* __restrict__ s0, __half* __restrict__ d0, int n0,
    const float* __restrict__ s1, __half* __restrict__ d1, int n1,
    const float* __restrict__ s2, __half* __restrict__ d2, int n2,
    const float* __restrict__ s3, __half* __restrict__ d3, int n3)
{
    int i = (blockIdx.x * 256 + threadIdx.x) * 4;
    const float* s; __half* d;
    if (i < n0)                { s = s0; d = d0; }
    else if ((i -= n0) < n1)   { s = s1; d = d1; }
    else if ((i -= n1) < n2)   { s = s2; d = d2; }
    else if ((i -= n2) < n3)   { s = s3; d = d3; }
    else return;
    float4 v = *(const float4*)(s + i);
    *(uint2*)(d + i) = make_uint2(pack2h(v.x, v.y), pack2h(v.z, v.w));
}

// ---------------------------------------------------------------------------
// fp16 tensor-core GEMM: C = A @ W^T + bias. CTA 128x128, BK=32, 256 threads
// (8 warps, warp tile 64x32), m16n8k16, 3-stage cp.async, ldmatrix frags.
// EPI: 1 = + w_b, fused transpose -> g_hT, fused src/dst projections
//      2 = GeLU  -> g_ff16 fp16
//      3 = + residual g_y -> g_pre2 fp32
// ---------------------------------------------------------------------------
#define LDKu 20
#define MSTG (128*LDKu)            // 2560 u32 per stage per matrix
#define MM_SMEM (3*MSTG*4*2)       // 61440 B

template<int EPI>
__global__ __launch_bounds__(256, 2) void mm_mma(
    const __half* __restrict__ A, const __half* __restrict__ W,
    const float* __restrict__ bias, const float* __restrict__ aw,
    int N, int K)
{
    extern __shared__ uint32_t smm[];
    uint32_t* As = smm;                 // [3][MSTG]
    uint32_t* Bs = smm + 3*MSTG;        // [3][MSTG]
    const uint32_t smmB = sm32(smm);

    const int tid  = threadIdx.x;
    const int wid  = tid >> 5;
    const int lane = tid & 31;
    const int g    = lane >> 2;
    const int t    = lane & 3;
    const int bm   = blockIdx.y << 7;
    const int bn   = blockIdx.x << 7;
    const int wm   = (wid & 1) << 6;   // 0/64
    const int wn   = (wid >> 1) << 5;  // 0/32/64/96

    int aOff[4], bOff[4];
    {
        const int la = lane & 15, ha = lane >> 4;
        const int lb = lane & 7,  hb = (lane >> 3) & 3;
        #pragma unroll
        for (int mi = 0; mi < 4; mi++)
            aOff[mi] = (wm + (mi << 4) + la) * LDKu + (ha << 2);
        #pragma unroll
        for (int ni = 0; ni < 4; ni++)
            bOff[ni] = (wn + (ni << 3) + lb) * LDKu + (hb << 2);
    }

    float acc[4][4][4];
    #pragma unroll
    for (int mi = 0; mi < 4; mi++)
        #pragma unroll
        for (int ni = 0; ni < 4; ni++)
            #pragma unroll
            for (int c = 0; c < 4; c++) acc[mi][ni][c] = 0.f;

    auto issue = [&](int kt, int slot) {
        const int k0 = kt << 5;
        #pragma unroll
        for (int u = 0; u < 2; u++) {
            const int idx = tid + (u << 8);
            const int r = idx >> 2, c = idx & 3;
            const __half* ga = A + (size_t)(bm + r) * K + k0 + (c << 3);
            const __half* gb = W + (size_t)(bn + r) * K + k0 + (c << 3);
            CP16(sm32(As + slot*MSTG + r*LDKu + (c << 2)), ga);
            CP16(sm32(Bs + slot*MSTG + r*LDKu + (c << 2)), gb);
        }
        CPCOMMIT();
    };

    const int nkt = K >> 5;
    issue(0, 0);
    issue(1, 1);

    for (int kt = 0; kt < nkt; kt++) {
        if (kt + 1 < nkt) { CPWAIT1(); } else { CPWAIT0(); }
        __syncthreads();
        if (kt + 2 < nkt) issue(kt + 2, (kt + 2) % 3);

        const uint32_t AbB = smmB + (((kt % 3) * MSTG) << 2);
        const uint32_t BbB = smmB + ((((kt % 3) + 3) * MSTG) << 2);

        uint32_t bfr[4][4];
        #pragma unroll
        for (int ni = 0; ni < 4; ni++)
            ldm_x4(bfr[ni], BbB + (bOff[ni] << 2));

        #pragma unroll
        for (int kc = 0; kc < 2; kc++) {
            uint32_t afr[4][4];
            #pragma unroll
            for (int mi = 0; mi < 4; mi++)
                ldm_x4(afr[mi], AbB + ((aOff[mi] + (kc << 3)) << 2));
            #pragma unroll
            for (int mi = 0; mi < 4; mi++)
                #pragma unroll
                for (int ni = 0; ni < 4; ni++)
                    mma16(acc[mi][ni], afr[mi], &bfr[ni][kc << 1]);
        }
    }

    // ---------------- epilogue ----------------
    if (EPI == 1) {
        // fused transpose -> g_hT (bh,d,s) + fused src/dst projections
        __syncthreads();
        __half* trsp = (__half*)smm;          // [128 cols][136 rows-pad] 34816 B
        float*  aws  = (float*)(smm + 9216);  // byte 36864: a_w copy (128 f)
        if (tid < 128) aws[tid] = aw[tid];
        #pragma unroll
        for (int ni = 0; ni < 4; ni++) {
            const int lcol = wn + (ni << 3) + (t << 1);
            const float2 bb = *(const float2*)&bias[bn + lcol];
            #pragma unroll
            for (int mi = 0; mi < 4; mi++) {
                #pragma unroll
                for (int half = 0; half < 2; half++) {
                    const int lrow = wm + (mi << 4) + g + (half << 3);
                    trsp[lcol * 136 + lrow]       = __float2half(acc[mi][ni][half*2+0] + bb.x);
                    trsp[(lcol + 1) * 136 + lrow] = __float2half(acc[mi][ni][half*2+1] + bb.y);
                }
            }
        }
        __syncthreads();
        const int bI = bm >> 9, s0 = bm & 511;
        #pragma unroll
        for (int u = 0; u < 8; u++) {
            const int idx = tid + (u << 8);      // 0..2047
            const int lc = idx >> 4;             // local col 0..127
            const int sc = (idx & 15) << 3;      // s offset 0..120
            uint4 val = *(uint4*)&trsp[lc * 136 + sc];
            const int col = bn + lc;
            const int hh = col >> 6, d = col & 63;
            *(uint4*)&g_hT[((size_t)((bI << 3) + hh) * HDim + d) * Ssz + s0 + sc] = val;
        }
        // src/dst: thread = (head-in-tile, s-row)
        {
            const int hh2 = tid >> 7, srow = tid & 127;
            float ssum = 0.f, dsum = 0.f;
            #pragma unroll 16
            for (int d = 0; d < 64; d++) {
                const float hv = __half2float(trsp[((hh2 << 6) + d) * 136 + srow]);
                ssum += hv * aws[d];
                dsum += hv * aws[64 + d];
            }
            const int bh = (bI << 3) + (bn >> 6) + hh2;
            g_src[bh * Ssz + s0 + srow] = ssum;
            g_dst[bh * Ssz + s0 + srow] = dsum;
        }
    } else {
        #pragma unroll
        for (int ni = 0; ni < 4; ni++) {
            const int col = bn + wn + (ni << 3) + (t << 1);
            const float2 bb = *(const float2*)&bias[col];
            #pragma unroll
            for (int mi = 0; mi < 4; mi++) {
                #pragma unroll
                for (int half = 0; half < 2; half++) {
                    const int row = bm + wm + (mi << 4) + g + (half << 3);
                    float2 v;
                    v.x = acc[mi][ni][half*2+0] + bb.x;
                    v.y = acc[mi][ni][half*2+1] + bb.y;
                    if (EPI == 2) {
                        v.x = 0.5f*v.x*(1.f + erff(v.x*0.70710678118654752f));
                        v.y = 0.5f*v.y*(1.f + erff(v.y*0.70710678118654752f));
                        *(uint32_t*)&g_ff16[(size_t)row * N + col] = pack2h(v.x, v.y);
                    } else {
                        const float2 rr = *(const float2*)&g_y[(size_t)row * Dsz + col];
                        v.x += rr.x; v.y += rr.y;
                        *(float2*)&g_pre2[(size_t)row * Dsz + col] = v;
                    }
                }
            }
        }
    }
}

// ---------------------------------------------------------------------------
// prep_kernel: per (b,h) -- rank d_j (ascending, index tiebreak), scalar
// prefix/suffix scans for Z, per-row cut point k_i + a1/a2, and a COUNTING
// SORT of rows by k_i (g_rows + g_kstart buckets) for the incremental kernel.
// ---------------------------------------------------------------------------
__global__ __launch_bounds__(256) void prep_kernel()
{
    __shared__ float dsm[512], e1[512], e2[512], e1s[512], e2s[512], ds[512];
    __shared__ float wtot[8];
    __shared__ int   hist[513], kst[513], kloc[512];
    const int bh = blockIdx.x, tid = threadIdx.x;
    const int lane = tid & 31, w = tid >> 5;

    for (int u = tid; u < 512; u += 256) {
        const float dv = g_dst[bh * 512 + u];
        dsm[u] = dv; e1[u] = __expf(dv); e2[u] = __expf(NEG_SLOPE * dv);
    }
    for (int u = tid; u < 513; u += 256) hist[u] = 0;
    __syncthreads();

    // rank + scatter to sorted order
    #pragma unroll
    for (int uu = 0; uu < 2; uu++) {
        const int j = tid + (uu << 8);
        const float dj = dsm[j];
        int r = 0;
        for (int jj = 0; jj < 512; jj++) {
            const float o = dsm[jj];
            r += (o < dj) || (o == dj && jj < j);
        }
        e1s[r] = e1[j]; e2s[r] = e2[j]; ds[r] = dj;
        g_perm[bh * 512 + r] = j;
    }
    __syncthreads();

    // inclusive PREFIX scan of e2s (in place)
    {
        const float v1 = e2s[2*tid + 1];
        float s = e2s[2*tid] + v1;
        #pragma unroll
        for (int off = 1; off < 32; off <<= 1) {
            const float n = __shfl_up_sync(0xffffffffu, s, off);
            if (lane >= off) s += n;
        }
        if (lane == 31) wtot[w] = s;
        __syncthreads();
        float offt = 0.f;
        for (int i2 = 0; i2 < w; i2++) offt += wtot[i2];
        const float inc = s + offt;
        e2s[2*tid + 1] = inc; e2s[2*tid] = inc - v1;
        __syncthreads();
    }
    // inclusive SUFFIX scan of e1s (in place)
    {
        const float v0 = e1s[2*tid];
        float s = v0 + e1s[2*tid + 1];
        #pragma unroll
        for (int off = 1; off < 32; off <<= 1) {
            const float n = __shfl_down_sync(0xffffffffu, s, off);
            if (lane + off < 32) s += n;
        }
        if (lane == 0) wtot[w] = s;
        __syncthreads();
        float offt = 0.f;
        for (int i2 = w + 1; i2 < 8; i2++) offt += wtot[i2];
        const float inc = s + offt;
        e1s[2*tid] = inc; e1s[2*tid + 1] = inc - v0;
        __syncthreads();
    }

    // per-row k_i (binary search), Z, and histogram
    #pragma unroll
    for (int uu = 0; uu < 2; uu++) {
        const int i = tid + (uu << 8);
        const float sv = g_src[bh * 512 + i];
        const float th = -sv;
        int lo = 0, hi = 512;
        while (lo < hi) { const int mid = (lo + hi) >> 1; if (ds[mid] < th) lo = mid + 1; else hi = mid; }
        const int k = lo;
        const float t1 = (k < 512) ? e1s[k] : 0.f;
        const float t2 = (k > 0) ? e2s[k - 1] : 0.f;
        const float e1i = __expf(sv), e2i = __expf(NEG_SLOPE * sv);
        const float invZ = 1.0f / (e1i * t1 + e2i * t2);
        g_a1[bh * 512 + i] = e1i * invZ;
        g_a2[bh * 512 + i] = e2i * invZ;
        kloc[i] = k;
        atomicAdd(&hist[k], 1);
    }
    __syncthreads();
    // exclusive scan of hist -> kst
    if (tid == 0) {
        int run = 0;
        for (int b = 0; b <= 512; b++) { kst[b] = run; run += hist[b]; }
    }
    __syncthreads();
    for (int u = tid; u < 513; u += 256) hist[u] = 0;   // reuse as cursor
    __syncthreads();
    #pragma unroll
    for (int uu = 0; uu < 2; uu++) {
        const int i = tid + (uu << 8);
        const int k = kloc[i];
        const int pos = kst[k] + atomicAdd(&hist[k], 1);
        g_rows[bh * 512 + pos] = i;
    }
    for (int u = tid; u < 513; u += 256) g_kstart[bh * 513 + u] = kst[u];
}

// ---------------------------------------------------------------------------
// attn_inc_kernel: block per (b,h); thread = (q, d), q = k-segment, d = dim.
// Running suffix/prefix vectors S1,S2 over sorted k; emit rows bucketed at k.
//   out[i,d] = a1_i * S1[d]@k_i + a2_i * S2[d]@k_i
// ---------------------------------------------------------------------------
__global__ __launch_bounds__(256) void attn_inc_kernel()
{
    __shared__ float e1[512], e2[512], a1s[512], a2s[512];
    __shared__ int   perm[512], rows[512], kst[513];
    __shared__ float S1seg[4][64], S2seg[4][64];

    const int bh  = blockIdx.x;
    const int tid = threadIdx.x;
    const int q = tid >> 6, d = tid & 63;

    for (int u = tid; u < 512; u += 256) {
        const float dv = g_dst[bh * 512 + u];
        e1[u] = __expf(dv); e2[u] = __expf(NEG_SLOPE * dv);
        perm[u] = g_perm[bh * 512 + u];
        rows[u] = g_rows[bh * 512 + u];
        a1s[u]  = g_a1  [bh * 512 + u];
        a2s[u]  = g_a2  [bh * 512 + u];
    }
    for (int u = tid; u < 513; u += 256) kst[u] = g_kstart[bh * 513 + u];
    __syncthreads();

    const __half* Hrow = g_hT + ((size_t)bh * 64 + d) * 512;

    // phase 1: per-segment partial sums
    const int k0 = q << 7;
    float p1 = 0.f, p2 = 0.f;
    for (int k = k0; k < k0 + 128; k++) {
        const int j = perm[k];
        const float h = __half2float(Hrow[j]);
        p1 += e1[j] * h; p2 += e2[j] * h;
    }
    S1seg[q][d] = p1; S2seg[q][d] = p2;
    __syncthreads();

    // phase 2: segment-start running values
    float S1 = 0.f, S2 = 0.f;
    #pragma unroll
    for (int qq = 0; qq < 4; qq++) {
        if (qq >= q) S1 += S1seg[qq][d];
        if (qq <  q) S2 += S2seg[qq][d];
    }

    // phase 3: walk k, emit rows, update
    float* attb = g_att + (size_t)(bh << 9) * 64;
    for (int k = k0; k < k0 + 128; k++) {
        const int rb = kst[k], re = kst[k + 1];
        for (int r = rb; r < re; r++) {
            const int i = rows[r];
            attb[(size_t)i * 64 + d] = a1s[i] * S1 + a2s[i] * S2;
        }
        const int j = perm[k];
        const float h = __half2float(Hrow[j]);
        S1 -= e1[j] * h;
        S2 += e2[j] * h;
    }
    if (q == 3) {       // bucket k = 512 (pure e2 rows)
        for (int r = kst[512]; r < 512; r++) {
            const int i = rows[r];
            attb[(size_t)i * 64 + d] = a1s[i] * S1 + a2s[i] * S2;
        }
    }
}

// ---------------------------------------------------------------------------
// LayerNorms: one WARP per row of 512; 16 elems/thread; shfl-only reduction
// ---------------------------------------------------------------------------
__global__ __launch_bounds__(256) void ln1_kernel(
    const float* __restrict__ x,
    const float* __restrict__ gw, const float* __restrict__ bw)
{
    const int m    = (blockIdx.x << 3) + (threadIdx.x >> 5);
    const int lane = threadIdx.x & 31;
    const int bb = m >> 9, s = m & 511;

    float v[16];
    float s1 = 0.f, s2 = 0.f;
    #pragma unroll
    for (int u = 0; u < 4; u++) {
        const int d = (u << 7) + (lane << 2);
        const int hh = d >> 6, hd = d & 63;
        const float4 a  = *(const float4*)&g_att[((size_t)(((bb << 3) + hh) << 9) + s) * HDim + hd];
        const float4 xv = *(const float4*)&x[(size_t)m * Dsz + d];
        v[u*4+0] = a.x + xv.x; v[u*4+1] = a.y + xv.y;
        v[u*4+2] = a.z + xv.z; v[u*4+3] = a.w + xv.w;
        #pragma unroll
        for (int k = 0; k < 4; k++) { s1 += v[u*4+k]; s2 += v[u*4+k]*v[u*4+k]; }
    }
    #pragma unroll
    for (int off = 16; off; off >>= 1) {
        s1 += __shfl_xor_sync(0xffffffffu, s1, off);
        s2 += __shfl_xor_sync(0xffffffffu, s2, off);
    }
    const float mean = s1 * (1.0f / 512.0f);
    const float rstd = rsqrtf(s2 * (1.0f / 512.0f) - mean * mean + 1e-5f);

    #pragma unroll
    for (int u = 0; u < 4; u++) {
        const int d = (u << 7) + (lane << 2);
        const float4 gg = *(const float4*)&gw[d];
        const float4 bbv = *(const float4*)&bw[d];
        float4 o;
        o.x = (v[u*4+0] - mean) * rstd * gg.x + bbv.x;
        o.y = (v[u*4+1] - mean) * rstd * gg.y + bbv.y;
        o.z = (v[u*4+2] - mean) * rstd * gg.z + bbv.z;
        o.w = (v[u*4+3] - mean) * rstd * gg.w + bbv.w;
        *(float4*)&g_y[(size_t)m * Dsz + d] = o;
        *(uint2*)&g_y16[(size_t)m * Dsz + d] = make_uint2(pack2h(o.x, o.y), pack2h(o.z, o.w));
    }
}

__global__ __launch_bounds__(256) void ln2_kernel(
    const float* __restrict__ gw, const float* __restrict__ bw,
    float* __restrict__ out)
{
    const int m    = (blockIdx.x << 3) + (threadIdx.x >> 5);
    const int lane = threadIdx.x & 31;

    float v[16];
    float s1 = 0.f, s2 = 0.f;
    #pragma unroll
    for (int u = 0; u < 4; u++) {
        const int d = (u << 7) + (lane << 2);
        const float4 p = *(const float4*)&g_pre2[(size_t)m * Dsz + d];
        v[u*4+0] = p.x; v[u*4+1] = p.y; v[u*4+2] = p.z; v[u*4+3] = p.w;
        #pragma unroll
        for (int k = 0; k < 4; k++) { s1 += v[u*4+k]; s2 += v[u*4+k]*v[u*4+k]; }
    }
    #pragma unroll
    for (int off = 16; off; off >>= 1) {
        s1 += __shfl_xor_sync(0xffffffffu, s1, off);
        s2 += __shfl_xor_sync(0xffffffffu, s2, off);
    }
    const float mean = s1 * (1.0f / 512.0f);
    const float rstd = rsqrtf(s2 * (1.0f / 512.0f) - mean * mean + 1e-5f);

    #pragma unroll
    for (int u = 0; u < 4; u++) {
        const int d = (u << 7) + (lane << 2);
        const float4 gg = *(const float4*)&gw[d];
        const float4 bbv = *(const float4*)&bw[d];
        float4 o;
        o.x = (v[u*4+0] - mean) * rstd * gg.x + bbv.x;
        o.y = (v[u*4+1] - mean) * rstd * gg.y + bbv.y;
        o.z = (v[u*4+2] - mean) * rstd * gg.z + bbv.z;
        o.w = (v[u*4+3] - mean) * rstd * gg.w + bbv.w;
        *(float4*)&out[(size_t)m * Dsz + d] = o;
    }
}

// ---------------------------------------------------------------------------
// Launch. adj/sem_W/sem_b are provably dead (softmax output can never be
// exactly 0, so the mask is the identity) and are not read.
// ---------------------------------------------------------------------------
extern "C" void kernel_launch(void* const* d_in, const int* in_sizes, int n_in,
                              void* d_out, int out_size)
{
    const float* x     = (const float*)d_in[0];
    const float* w_W   = (const float*)d_in[2];
    const float* w_b   = (const float*)d_in[3];
    const float* a_w   = (const float*)d_in[4];
    const float* ff1_W = (const float*)d_in[7];
    const float* ff1_b = (const float*)d_in[8];
    const float* ff2_W = (const float*)d_in[9];
    const float* ff2_b = (const float*)d_in[10];
    const float* ln1_g = (const float*)d_in[11];
    const float* ln1_b = (const float*)d_in[12];
    const float* ln2_g = (const float*)d_in[13];
    const float* ln2_b = (const float*)d_in[14];
    float* out = (float*)d_out;

    __half* dx16;  cudaGetSymbolAddress((void**)&dx16,  g_x16);
    __half* dw16;  cudaGetSymbolAddress((void**)&dw16,  g_w16);
    __half* d1w16; cudaGetSymbolAddress((void**)&d1w16, g_f1w16);
    __half* d2w16; cudaGetSymbolAddress((void**)&d2w16, g_f2w16);
    __half* dy16;  cudaGetSymbolAddress((void**)&dy16,  g_y16);
    __half* dff16; cudaGetSymbolAddress((void**)&dff16, g_ff16);

    cudaFuncSetAttribute(mm_mma<1>, cudaFuncAttributeMaxDynamicSharedMemorySize, MM_SMEM);
    cudaFuncSetAttribute(mm_mma<2>, cudaFuncAttributeMaxDynamicSharedMemorySize, MM_SMEM);
    cudaFuncSetAttribute(mm_mma<3>, cudaFuncAttributeMaxDynamicSharedMemorySize, MM_SMEM);

    // 0) fp32 -> fp16 conversions (single fused launch)
    const int n0 = Mrows*Dsz, n1 = Dsz*Dsz, n2 = 2*Dsz*Dsz, n3 = 2*Dsz*Dsz;
    f2h4_kernel<<<(n0+n1+n2+n3)/1024, 256>>>(x, dx16, n0, w_W, dw16, n1,
                                             ff1_W, d1w16, n2, ff2_W, d2w16, n3);

    // 1) h = x @ w_W^T + w_b -> g_hT (bh,d,s) + fused src/dst projections
    mm_mma<1><<<dim3(Dsz/128, Mrows/128), 256, MM_SMEM>>>(dx16, dw16, w_b, a_w, Dsz, Dsz);
    // 2) rank + scans + cut points + counting sort
    prep_kernel<<<Bsz*Hh, 256>>>();
    // 3) attention via incremental sorted scans -> g_att
    attn_inc_kernel<<<Bsz*Hh, 256>>>();
    // 4) LN1(att + x) -> g_y (fp32) + g_y16
    ln1_kernel<<<Mrows/8, 256>>>(x, ln1_g, ln1_b);
    // 5) g_ff16 = GeLU(y @ ff1_W^T + ff1_b)
    mm_mma<2><<<dim3(2*Dsz/128, Mrows/128), 256, MM_SMEM>>>(dy16, d1w16, ff1_b, nullptr, 2*Dsz, Dsz);
    // 6) g_pre2 = ff @ ff2_W^T + ff2_b + y
    mm_mma<3><<<dim3(Dsz/128, Mrows/128), 256, MM_SMEM>>>(dff16, d2w16, ff2_b, nullptr, Dsz, 2*Dsz);
    // 7) LN2 -> out
    ln2_kernel<<<Mrows/8, 256>>>(ln2_g, ln2_b, out);
}

// round 16
// speedup vs baseline: 1.2875x; 1.2875x over previous
#include <cuda_runtime.h>
#include <cuda_fp16.h>
#include <math.h>
#include <stdint.h>

// Problem constants
#define Bsz 32
#define Ssz 512
#define Dsz 512
#define Hh  8
#define HDim 64
#define Mrows (Bsz*Ssz)          // 16384
#define NEG_SLOPE 0.2f

// ---------------------------------------------------------------------------
// Scratch (static __device__ arrays; allocation is forbidden)
// ---------------------------------------------------------------------------
__device__ __half g_x16 [Mrows*Dsz];         // x in fp16
__device__ __half g_w16 [Dsz*Dsz];           // w_W fp16
__device__ __half g_f1w16[2*Dsz*Dsz];        // ff1_W fp16
__device__ __half g_f2w16[2*Dsz*Dsz];        // ff2_W fp16
__device__ __half g_hT  [Bsz*Hh*HDim*Ssz];   // (bh, d, s) fp16 transposed heads
__device__ float  g_src [Bsz*Hh*Ssz];
__device__ float  g_dst [Bsz*Hh*Ssz];
__device__ int    g_perm[Bsz*Hh*Ssz];        // sorted order (rank -> j)
__device__ int    g_k   [Bsz*Hh*Ssz];        // per-row cut point
__device__ float  g_a1  [Bsz*Hh*Ssz];        // e^{s_i}/Z_i
__device__ float  g_a2  [Bsz*Hh*Ssz];        // e^{0.2 s_i}/Z_i
__device__ float  g_att [Bsz*Hh*Ssz*HDim];   // attention output fp32
__device__ float  g_y   [Mrows*Dsz];         // post-LN1 fp32 (residual for EPI3)
__device__ __half g_y16 [Mrows*Dsz];         // post-LN1 fp16 (mm2 input)
__device__ __half g_ff16[Mrows*2*Dsz];       // GeLU(ff1) fp16 (mm3 input)
__device__ float  g_pre2[Mrows*Dsz];         // ff2 out + residual (pre-LN2)

// ---------------------------------------------------------------------------
// helpers
// ---------------------------------------------------------------------------
__device__ __forceinline__ uint32_t pack2h(float x, float y) {
    __half2 h = __floats2half2_rn(x, y);
    return *reinterpret_cast<uint32_t*>(&h);
}
__device__ __forceinline__ uint32_t sm32(const void* p) {
    return (uint32_t)__cvta_generic_to_shared(p);
}
__device__ __forceinline__ void mma16(float* c, const uint32_t* a, const uint32_t* b) {
    asm volatile(
        "mma.sync.aligned.m16n8k16.row.col.f32.f16.f16.f32 "
        "{%0,%1,%2,%3}, {%4,%5,%6,%7}, {%8,%9}, {%0,%1,%2,%3};"
        : "+f"(c[0]), "+f"(c[1]), "+f"(c[2]), "+f"(c[3])
        : "r"(a[0]), "r"(a[1]), "r"(a[2]), "r"(a[3]), "r"(b[0]), "r"(b[1]));
}
__device__ __forceinline__ void ldm_x4(uint32_t* r, uint32_t saddr) {
    asm volatile(
        "ldmatrix.sync.aligned.m8n8.x4.shared.b16 {%0,%1,%2,%3}, [%4];"
        : "=r"(r[0]), "=r"(r[1]), "=r"(r[2]), "=r"(r[3]) : "r"(saddr));
}
#define CP16(sa, ga) asm volatile("cp.async.cg.shared.global [%0], [%1], 16;" :: "r"(sa), "l"(ga))
#define CPCOMMIT()   asm volatile("cp.async.commit_group;" ::: "memory")
#define CPWAIT1()    asm volatile("cp.async.wait_group 1;" ::: "memory")
#define CPWAIT0()    asm volatile("cp.async.wait_group 0;" ::: "memory")

// ---------------------------------------------------------------------------
// fused fp32 -> fp16 conversion of 4 arrays (all sizes % 1024 == 0)
// ---------------------------------------------------------------------------
__global__ __launch_bounds__(256) void f2h4_kernel(
    const float* __restrict__ s0, __half* __restrict__ d0, int n0,
    const float* __restrict__ s1, __half* __restrict__ d1, int n1,
    const float* __restrict__ s2, __half* __restrict__ d2, int n2,
    const float* __restrict__ s3, __half* __restrict__ d3, int n3)
{
    int i = (blockIdx.x * 256 + threadIdx.x) * 4;
    const float* s; __half* d;
    if (i < n0)                { s = s0; d = d0; }
    else if ((i -= n0) < n1)   { s = s1; d = d1; }
    else if ((i -= n1) < n2)   { s = s2; d = d2; }
    else if ((i -= n2) < n3)   { s = s3; d = d3; }
    else return;
    float4 v = *(const float4*)(s + i);
    *(uint2*)(d + i) = make_uint2(pack2h(v.x, v.y), pack2h(v.z, v.w));
}

// ---------------------------------------------------------------------------
// fp16 tensor-core GEMM: C = A @ W^T + bias. CTA 128x128, BK=32, 256 threads
// (8 warps, warp tile 64x32), m16n8k16, 3-stage cp.async, ldmatrix frags.
// EPI: 1 = + w_b, fused transpose -> g_hT, fused src/dst projections
//      2 = GeLU  -> g_ff16 fp16
//      3 = + residual g_y -> g_pre2 fp32
// ---------------------------------------------------------------------------
#define LDKu 20
#define MSTG (128*LDKu)            // 2560 u32 per stage per matrix
#define MM_SMEM (3*MSTG*4*2)       // 61440 B

template<int EPI>
__global__ __launch_bounds__(256, 2) void mm_mma(
    const __half* __restrict__ A, const __half* __restrict__ W,
    const float* __restrict__ bias, const float* __restrict__ aw,
    int N, int K)
{
    extern __shared__ uint32_t smm[];
    uint32_t* As = smm;                 // [3][MSTG]
    uint32_t* Bs = smm + 3*MSTG;        // [3][MSTG]
    const uint32_t smmB = sm32(smm);

    const int tid  = threadIdx.x;
    const int wid  = tid >> 5;
    const int lane = tid & 31;
    const int g    = lane >> 2;
    const int t    = lane & 3;
    const int bm   = blockIdx.y << 7;
    const int bn   = blockIdx.x << 7;
    const int wm   = (wid & 1) << 6;   // 0/64
    const int wn   = (wid >> 1) << 5;  // 0/32/64/96

    int aOff[4], bOff[4];
    {
        const int la = lane & 15, ha = lane >> 4;
        const int lb = lane & 7,  hb = (lane >> 3) & 3;
        #pragma unroll
        for (int mi = 0; mi < 4; mi++)
            aOff[mi] = (wm + (mi << 4) + la) * LDKu + (ha << 2);
        #pragma unroll
        for (int ni = 0; ni < 4; ni++)
            bOff[ni] = (wn + (ni << 3) + lb) * LDKu + (hb << 2);
    }

    float acc[4][4][4];
    #pragma unroll
    for (int mi = 0; mi < 4; mi++)
        #pragma unroll
        for (int ni = 0; ni < 4; ni++)
            #pragma unroll
            for (int c = 0; c < 4; c++) acc[mi][ni][c] = 0.f;

    auto issue = [&](int kt, int slot) {
        const int k0 = kt << 5;
        #pragma unroll
        for (int u = 0; u < 2; u++) {
            const int idx = tid + (u << 8);
            const int r = idx >> 2, c = idx & 3;
            const __half* ga = A + (size_t)(bm + r) * K + k0 + (c << 3);
            const __half* gb = W + (size_t)(bn + r) * K + k0 + (c << 3);
            CP16(sm32(As + slot*MSTG + r*LDKu + (c << 2)), ga);
            CP16(sm32(Bs + slot*MSTG + r*LDKu + (c << 2)), gb);
        }
        CPCOMMIT();
    };

    const int nkt = K >> 5;
    issue(0, 0);
    issue(1, 1);

    for (int kt = 0; kt < nkt; kt++) {
        if (kt + 1 < nkt) { CPWAIT1(); } else { CPWAIT0(); }
        __syncthreads();
        if (kt + 2 < nkt) issue(kt + 2, (kt + 2) % 3);

        const uint32_t AbB = smmB + (((kt % 3) * MSTG) << 2);
        const uint32_t BbB = smmB + ((((kt % 3) + 3) * MSTG) << 2);

        uint32_t bfr[4][4];
        #pragma unroll
        for (int ni = 0; ni < 4; ni++)
            ldm_x4(bfr[ni], BbB + (bOff[ni] << 2));

        #pragma unroll
        for (int kc = 0; kc < 2; kc++) {
            uint32_t afr[4][4];
            #pragma unroll
            for (int mi = 0; mi < 4; mi++)
                ldm_x4(afr[mi], AbB + ((aOff[mi] + (kc << 3)) << 2));
            #pragma unroll
            for (int mi = 0; mi < 4; mi++)
                #pragma unroll
                for (int ni = 0; ni < 4; ni++)
                    mma16(acc[mi][ni], afr[mi], &bfr[ni][kc << 1]);
        }
    }

    // ---------------- epilogue ----------------
    if (EPI == 1) {
        // fused transpose -> g_hT (bh,d,s) + fused src/dst projections
        __syncthreads();
        __half* trsp = (__half*)smm;          // [128 cols][136 rows-pad] 34816 B
        float*  aws  = (float*)(smm + 9216);  // byte 36864: a_w copy (128 f)
        if (tid < 128) aws[tid] = aw[tid];
        #pragma unroll
        for (int ni = 0; ni < 4; ni++) {
            const int lcol = wn + (ni << 3) + (t << 1);
            const float2 bb = *(const float2*)&bias[bn + lcol];
            #pragma unroll
            for (int mi = 0; mi < 4; mi++) {
                #pragma unroll
                for (int half = 0; half < 2; half++) {
                    const int lrow = wm + (mi << 4) + g + (half << 3);
                    trsp[lcol * 136 + lrow]       = __float2half(acc[mi][ni][half*2+0] + bb.x);
                    trsp[(lcol + 1) * 136 + lrow] = __float2half(acc[mi][ni][half*2+1] + bb.y);
                }
            }
        }
        __syncthreads();
        const int bI = bm >> 9, s0 = bm & 511;
        #pragma unroll
        for (int u = 0; u < 8; u++) {
            const int idx = tid + (u << 8);      // 0..2047
            const int lc = idx >> 4;             // local col 0..127
            const int sc = (idx & 15) << 3;      // s offset 0..120
            uint4 val = *(uint4*)&trsp[lc * 136 + sc];
            const int col = bn + lc;
            const int hh = col >> 6, d = col & 63;
            *(uint4*)&g_hT[((size_t)((bI << 3) + hh) * HDim + d) * Ssz + s0 + sc] = val;
        }
        // src/dst: thread = (head-in-tile, s-row)
        {
            const int hh2 = tid >> 7, srow = tid & 127;
            float ssum = 0.f, dsum = 0.f;
            #pragma unroll 16
            for (int d = 0; d < 64; d++) {
                const float hv = __half2float(trsp[((hh2 << 6) + d) * 136 + srow]);
                ssum += hv * aws[d];
                dsum += hv * aws[64 + d];
            }
            const int bh = (bI << 3) + (bn >> 6) + hh2;
            g_src[bh * Ssz + s0 + srow] = ssum;
            g_dst[bh * Ssz + s0 + srow] = dsum;
        }
    } else {
        #pragma unroll
        for (int ni = 0; ni < 4; ni++) {
            const int col = bn + wn + (ni << 3) + (t << 1);
            const float2 bb = *(const float2*)&bias[col];
            #pragma unroll
            for (int mi = 0; mi < 4; mi++) {
                #pragma unroll
                for (int half = 0; half < 2; half++) {
                    const int row = bm + wm + (mi << 4) + g + (half << 3);
                    float2 v;
                    v.x = acc[mi][ni][half*2+0] + bb.x;
                    v.y = acc[mi][ni][half*2+1] + bb.y;
                    if (EPI == 2) {
                        v.x = 0.5f*v.x*(1.f + erff(v.x*0.70710678118654752f));
                        v.y = 0.5f*v.y*(1.f + erff(v.y*0.70710678118654752f));
                        *(uint32_t*)&g_ff16[(size_t)row * N + col] = pack2h(v.x, v.y);
                    } else {
                        const float2 rr = *(const float2*)&g_y[(size_t)row * Dsz + col];
                        v.x += rr.x; v.y += rr.y;
                        *(float2*)&g_pre2[(size_t)row * Dsz + col] = v;
                    }
                }
            }
        }
    }
}

// ---------------------------------------------------------------------------
// prep_kernel: per (b,h) -- rank d_j (ascending, index tiebreak), scalar
// prefix/suffix scans for Z, per-row cut point k_i and normalizers a1,a2.
// ---------------------------------------------------------------------------
__global__ __launch_bounds__(256) void prep_kernel()
{
    __shared__ float dsm[512], e1[512], e2[512], e1s[512], e2s[512], ds[512];
    __shared__ float wtot[8];
    const int bh = blockIdx.x, tid = threadIdx.x;
    const int lane = tid & 31, w = tid >> 5;

    for (int u = tid; u < 512; u += 256) {
        const float dv = g_dst[bh * 512 + u];
        dsm[u] = dv; e1[u] = __expf(dv); e2[u] = __expf(NEG_SLOPE * dv);
    }
    __syncthreads();

    // rank + scatter to sorted order
    #pragma unroll
    for (int uu = 0; uu < 2; uu++) {
        const int j = tid + (uu << 8);
        const float dj = dsm[j];
        int r = 0;
        for (int jj = 0; jj < 512; jj++) {
            const float o = dsm[jj];
            r += (o < dj) || (o == dj && jj < j);
        }
        e1s[r] = e1[j]; e2s[r] = e2[j]; ds[r] = dj;
        g_perm[bh * 512 + r] = j;
    }
    __syncthreads();

    // inclusive PREFIX scan of e2s (in place)
    {
        const float v1 = e2s[2*tid + 1];
        float s = e2s[2*tid] + v1;
        #pragma unroll
        for (int off = 1; off < 32; off <<= 1) {
            const float n = __shfl_up_sync(0xffffffffu, s, off);
            if (lane >= off) s += n;
        }
        if (lane == 31) wtot[w] = s;
        __syncthreads();
        float offt = 0.f;
        for (int i2 = 0; i2 < w; i2++) offt += wtot[i2];
        const float inc = s + offt;
        e2s[2*tid + 1] = inc; e2s[2*tid] = inc - v1;
        __syncthreads();
    }
    // inclusive SUFFIX scan of e1s (in place)
    {
        const float v0 = e1s[2*tid];
        float s = v0 + e1s[2*tid + 1];
        #pragma unroll
        for (int off = 1; off < 32; off <<= 1) {
            const float n = __shfl_down_sync(0xffffffffu, s, off);
            if (lane + off < 32) s += n;
        }
        if (lane == 0) wtot[w] = s;
        __syncthreads();
        float offt = 0.f;
        for (int i2 = w + 1; i2 < 8; i2++) offt += wtot[i2];
        const float inc = s + offt;
        e1s[2*tid] = inc; e1s[2*tid + 1] = inc - v0;
        __syncthreads();
    }

    // per-row k_i (binary search) and Z
    #pragma unroll
    for (int uu = 0; uu < 2; uu++) {
        const int i = tid + (uu << 8);
        const float sv = g_src[bh * 512 + i];
        const float th = -sv;
        int lo = 0, hi = 512;
        while (lo < hi) { const int mid = (lo + hi) >> 1; if (ds[mid] < th) lo = mid + 1; else hi = mid; }
        const int k = lo;
        const float t1 = (k < 512) ? e1s[k] : 0.f;
        const float t2 = (k > 0) ? e2s[k - 1] : 0.f;
        const float e1i = __expf(sv), e2i = __expf(NEG_SLOPE * sv);
        const float invZ = 1.0f / (e1i * t1 + e2i * t2);
        g_k [bh * 512 + i] = k;
        g_a1[bh * 512 + i] = e1i * invZ;
        g_a2[bh * 512 + i] = e2i * invZ;
    }
}

// ---------------------------------------------------------------------------
// attn_scan_kernel v2: grid (8 d-chunks, 256 bh), DC=8 dims per block.
// Gather conflict-free (thread owns p, loops d), skew ph = p + (p>>5),
// row stride 529 (d-stride 17 banks, seg-stride 1 bank). 16 segments x 32.
// out[i,d] = a1_i * SUF1[k_i][d] + a2_i * PRE2[k_i-1][d].
// ---------------------------------------------------------------------------
#define DC 8
#define GROW 529
#define ASC_SMEM 55360
__global__ __launch_bounds__(256, 4) void attn_scan_kernel()
{
    extern __shared__ char sm[];
    __half* Hc  = (__half*)sm;                        // 8*512 halfs    (8192 B)
    float* G1   = (float*)(sm + 8192);                // 8*529 fp32    (16928 B)
    float* G2   = (float*)(sm + 8192 + 16928);        // 8*529 fp32    (16928 B)
    float* e1   = (float*)(sm + 8192 + 2*16928);      // 512
    float* e2   = e1 + 512;
    float* a1s  = e2 + 512;
    float* a2s  = a1s + 512;
    int*  perm  = (int*)(a2s + 512);
    int*  kk    = perm + 512;
    float* segs = (float*)(kk + 512);                 // 256

    const int bh = blockIdx.y, dc = blockIdx.x << 3;
    const int tid = threadIdx.x;

    for (int u = tid; u < 512; u += 256) {
        const float dv = g_dst[bh * 512 + u];
        e1[u] = __expf(dv); e2[u] = __expf(NEG_SLOPE * dv);
        perm[u] = g_perm[bh * 512 + u];
        kk[u]   = g_k   [bh * 512 + u];
        a1s[u]  = g_a1  [bh * 512 + u];
        a2s[u]  = g_a2  [bh * 512 + u];
    }
    for (int u = tid; u < 512; u += 256) {
        const int d = u >> 6, s8 = (u & 63) << 3;
        *(uint4*)&Hc[d * 512 + s8] =
            *(const uint4*)&g_hT[((size_t)(bh * 64 + dc + d)) * 512 + s8];
    }
    __syncthreads();

    // gather into sorted order: thread owns p (consecutive in warp), loops d
    #pragma unroll
    for (int uu = 0; uu < 2; uu++) {
        const int p = tid + (uu << 8);
        const int j = perm[p];
        const float f1 = e1[j], f2 = e2[j];
        const int ph = p + (p >> 5);
        #pragma unroll
        for (int d = 0; d < DC; d++) {
            const float hv = __half2float(Hc[d * 512 + j]);
            G1[d * GROW + ph] = f1 * hv;
            G2[d * GROW + ph] = f2 * hv;
        }
    }
    __syncthreads();

    // segmented scans: thread = (type, d, seg16); seg covers 32 p (33 phys)
    {
        const int type = tid >> 7, d = (tid >> 4) & 7, seg = tid & 15;
        float* G = type ? G2 : G1;
        const int base = d * GROW + seg * 33;
        float ssum = 0.f;
        #pragma unroll 8
        for (int i = 0; i < 32; i++) ssum += G[base + i];
        segs[tid] = ssum;
        __syncthreads();
        float off = 0.f;
        if (type == 0) { for (int s2 = seg + 1; s2 < 16; s2++) off += segs[(tid & ~15) + s2]; }
        else           { for (int s2 = 0; s2 < seg; s2++)      off += segs[(tid & ~15) + s2]; }
        float run = off;
        if (type == 0) { for (int i = 31; i >= 0; i--) { run += G[base + i]; G[base + i] = run; } }
        else           { for (int i = 0; i < 32; i++)  { run += G[base + i]; G[base + i] = run; } }
    }
    __syncthreads();

    // outputs: 4096 = 512 i x 8 d
    for (int idx = tid; idx < 4096; idx += 256) {
        const int i = idx >> 3, d = idx & 7;
        const int k = kk[i];
        const float t1 = (k < 512) ? G1[d * GROW + k + (k >> 5)] : 0.f;
        const int km = k - 1;
        const float t2 = (k > 0) ? G2[d * GROW + km + (km >> 5)] : 0.f;
        g_att[((size_t)(bh << 9) + i) * 64 + dc + d] = a1s[i] * t1 + a2s[i] * t2;
    }
}

// ---------------------------------------------------------------------------
// LayerNorms: one WARP per row of 512; 16 elems/thread; shfl-only reduction
// ---------------------------------------------------------------------------
__global__ __launch_bounds__(256) void ln1_kernel(
    const float* __restrict__ x,
    const float* __restrict__ gw, const float* __restrict__ bw)
{
    const int m    = (blockIdx.x << 3) + (threadIdx.x >> 5);
    const int lane = threadIdx.x & 31;
    const int bb = m >> 9, s = m & 511;

    float v[16];
    float s1 = 0.f, s2 = 0.f;
    #pragma unroll
    for (int u = 0; u < 4; u++) {
        const int d = (u << 7) + (lane << 2);
        const int hh = d >> 6, hd = d & 63;
        const float4 a  = *(const float4*)&g_att[((size_t)(((bb << 3) + hh) << 9) + s) * HDim + hd];
        const float4 xv = *(const float4*)&x[(size_t)m * Dsz + d];
        v[u*4+0] = a.x + xv.x; v[u*4+1] = a.y + xv.y;
        v[u*4+2] = a.z + xv.z; v[u*4+3] = a.w + xv.w;
        #pragma unroll
        for (int k = 0; k < 4; k++) { s1 += v[u*4+k]; s2 += v[u*4+k]*v[u*4+k]; }
    }
    #pragma unroll
    for (int off = 16; off; off >>= 1) {
        s1 += __shfl_xor_sync(0xffffffffu, s1, off);
        s2 += __shfl_xor_sync(0xffffffffu, s2, off);
    }
    const float mean = s1 * (1.0f / 512.0f);
    const float rstd = rsqrtf(s2 * (1.0f / 512.0f) - mean * mean + 1e-5f);

    #pragma unroll
    for (int u = 0; u < 4; u++) {
        const int d = (u << 7) + (lane << 2);
        const float4 gg = *(const float4*)&gw[d];
        const float4 bbv = *(const float4*)&bw[d];
        float4 o;
        o.x = (v[u*4+0] - mean) * rstd * gg.x + bbv.x;
        o.y = (v[u*4+1] - mean) * rstd * gg.y + bbv.y;
        o.z = (v[u*4+2] - mean) * rstd * gg.z + bbv.z;
        o.w = (v[u*4+3] - mean) * rstd * gg.w + bbv.w;
        *(float4*)&g_y[(size_t)m * Dsz + d] = o;
        *(uint2*)&g_y16[(size_t)m * Dsz + d] = make_uint2(pack2h(o.x, o.y), pack2h(o.z, o.w));
    }
}

__global__ __launch_bounds__(256) void ln2_kernel(
    const float* __restrict__ gw, const float* __restrict__ bw,
    float* __restrict__ out)
{
    const int m    = (blockIdx.x << 3) + (threadIdx.x >> 5);
    const int lane = threadIdx.x & 31;

    float v[16];
    float s1 = 0.f, s2 = 0.f;
    #pragma unroll
    for (int u = 0; u < 4; u++) {
        const int d = (u << 7) + (lane << 2);
        const float4 p = *(const float4*)&g_pre2[(size_t)m * Dsz + d];
        v[u*4+0] = p.x; v[u*4+1] = p.y; v[u*4+2] = p.z; v[u*4+3] = p.w;
        #pragma unroll
        for (int k = 0; k < 4; k++) { s1 += v[u*4+k]; s2 += v[u*4+k]*v[u*4+k]; }
    }
    #pragma unroll
    for (int off = 16; off; off >>= 1) {
        s1 += __shfl_xor_sync(0xffffffffu, s1, off);
        s2 += __shfl_xor_sync(0xffffffffu, s2, off);
    }
    const float mean = s1 * (1.0f / 512.0f);
    const float rstd = rsqrtf(s2 * (1.0f / 512.0f) - mean * mean + 1e-5f);

    #pragma unroll
    for (int u = 0; u < 4; u++) {
        const int d = (u << 7) + (lane << 2);
        const float4 gg = *(const float4*)&gw[d];
        const float4 bbv = *(const float4*)&bw[d];
        float4 o;
        o.x = (v[u*4+0] - mean) * rstd * gg.x + bbv.x;
        o.y = (v[u*4+1] - mean) * rstd * gg.y + bbv.y;
        o.z = (v[u*4+2] - mean) * rstd * gg.z + bbv.z;
        o.w = (v[u*4+3] - mean) * rstd * gg.w + bbv.w;
        *(float4*)&out[(size_t)m * Dsz + d] = o;
    }
}

// ---------------------------------------------------------------------------
// Launch. adj/sem_W/sem_b are provably dead (softmax output can never be
// exactly 0, so the mask is the identity) and are not read.
// ---------------------------------------------------------------------------
extern "C" void kernel_launch(void* const* d_in, const int* in_sizes, int n_in,
                              void* d_out, int out_size)
{
    const float* x     = (const float*)d_in[0];
    const float* w_W   = (const float*)d_in[2];
    const float* w_b   = (const float*)d_in[3];
    const float* a_w   = (const float*)d_in[4];
    const float* ff1_W = (const float*)d_in[7];
    const float* ff1_b = (const float*)d_in[8];
    const float* ff2_W = (const float*)d_in[9];
    const float* ff2_b = (const float*)d_in[10];
    const float* ln1_g = (const float*)d_in[11];
    const float* ln1_b = (const float*)d_in[12];
    const float* ln2_g = (const float*)d_in[13];
    const float* ln2_b = (const float*)d_in[14];
    float* out = (float*)d_out;

    __half* dx16;  cudaGetSymbolAddress((void**)&dx16,  g_x16);
    __half* dw16;  cudaGetSymbolAddress((void**)&dw16,  g_w16);
    __half* d1w16; cudaGetSymbolAddress((void**)&d1w16, g_f1w16);
    __half* d2w16; cudaGetSymbolAddress((void**)&d2w16, g_f2w16);
    __half* dy16;  cudaGetSymbolAddress((void**)&dy16,  g_y16);
    __half* dff16; cudaGetSymbolAddress((void**)&dff16, g_ff16);

    cudaFuncSetAttribute(mm_mma<1>, cudaFuncAttributeMaxDynamicSharedMemorySize, MM_SMEM);
    cudaFuncSetAttribute(mm_mma<2>, cudaFuncAttributeMaxDynamicSharedMemorySize, MM_SMEM);
    cudaFuncSetAttribute(mm_mma<3>, cudaFuncAttributeMaxDynamicSharedMemorySize, MM_SMEM);
    cudaFuncSetAttribute(attn_scan_kernel, cudaFuncAttributeMaxDynamicSharedMemorySize, ASC_SMEM);

    // 0) fp32 -> fp16 conversions (single fused launch)
    const int n0 = Mrows*Dsz, n1 = Dsz*Dsz, n2 = 2*Dsz*Dsz, n3 = 2*Dsz*Dsz;
    f2h4_kernel<<<(n0+n1+n2+n3)/1024, 256>>>(x, dx16, n0, w_W, dw16, n1,
                                             ff1_W, d1w16, n2, ff2_W, d2w16, n3);

    // 1) h = x @ w_W^T + w_b -> g_hT (bh,d,s) + fused src/dst projections
    mm_mma<1><<<dim3(Dsz/128, Mrows/128), 256, MM_SMEM>>>(dx16, dw16, w_b, a_w, Dsz, Dsz);
    // 2) rank + scans + cut points
    prep_kernel<<<Bsz*Hh, 256>>>();
    // 3) attention via sorted prefix/suffix scans -> g_att
    attn_scan_kernel<<<dim3(8, Bsz*Hh), 256, ASC_SMEM>>>();
    // 4) LN1(att + x) -> g_y (fp32) + g_y16
    ln1_kernel<<<Mrows/8, 256>>>(x, ln1_g, ln1_b);
    // 5) g_ff16 = GeLU(y @ ff1_W^T + ff1_b)
    mm_mma<2><<<dim3(2*Dsz/128, Mrows/128), 256, MM_SMEM>>>(dy16, d1w16, ff1_b, nullptr, 2*Dsz, Dsz);
    // 6) g_pre2 = ff @ ff2_W^T + ff2_b + y
    mm_mma<3><<<dim3(Dsz/128, Mrows/128), 256, MM_SMEM>>>(dff16, d2w16, ff2_b, nullptr, Dsz, 2*Dsz);
    // 7) LN2 -> out
    ln2_kernel<<<Mrows/8, 256>>>(ln2_g, ln2_b, out);
}